// round 1
// baseline (speedup 1.0000x reference)
#include <cuda_runtime.h>
#include <math.h>

// Problem dims (fixed by reference)
#define NB 4
#define NS 2048
#define ND 1024
#define NH 16
#define NHD 64
#define MTOT (NB * NS)   // 8192 rows for the projection GEMMs

// ---------------------------------------------------------------------------
// Scratch (device-global: no cudaMalloc allowed anywhere)
// ---------------------------------------------------------------------------
__device__ float g_Q[NB * NS * ND];
__device__ float g_K[NB * NS * ND];
__device__ float g_V[NB * NS * ND];
__device__ float g_C[NB * NS * ND];

// ---------------------------------------------------------------------------
// GEMM (NT):  C[m,n] = sum_k A[m,k] * W[n,k]  (+ optional bias[n])
// A: [M,K] row-major, W: [N,K] row-major (torch Linear weight), C: [M,N].
// BM=BN=128, BK=16, 256 threads, 8x8 register tile per thread.
// M,N multiples of 128; K multiple of 16 (true here: 8192/1024/1024).
// ---------------------------------------------------------------------------
template <bool BIAS>
__global__ __launch_bounds__(256) void gemm_nt(
    const float* __restrict__ A, const float* __restrict__ W,
    const float* __restrict__ bias, float* __restrict__ C,
    int M, int N, int K)
{
    constexpr int BM = 128, BN = 128, BK = 16, PAD = 4;
    __shared__ float As[BK][BM + PAD];
    __shared__ float Bs[BK][BN + PAD];

    const int tid = threadIdx.x;
    const int tx  = tid & 15;        // 0..15 -> 8 output cols each
    const int ty  = tid >> 4;        // 0..15 -> 8 output rows each
    const int rowBase = blockIdx.y * BM;
    const int colBase = blockIdx.x * BN;

    float acc[8][8];
#pragma unroll
    for (int i = 0; i < 8; i++)
#pragma unroll
        for (int j = 0; j < 8; j++) acc[i][j] = 0.0f;

    for (int k0 = 0; k0 < K; k0 += BK) {
        // Load A-tile and W-tile (each 128x16 floats), transposed into smem.
        // 512 float4 per tile; 256 threads x 2 vectors.
#pragma unroll
        for (int v = 0; v < 2; v++) {
            int f = tid + v * 256;       // float4 index 0..511
            int r = f >> 2;              // 0..127 tile row
            int c = (f & 3) << 2;        // 0,4,8,12 within BK
            float4 a = *(const float4*)(A + (size_t)(rowBase + r) * K + k0 + c);
            As[c + 0][r] = a.x; As[c + 1][r] = a.y;
            As[c + 2][r] = a.z; As[c + 3][r] = a.w;
            float4 b = *(const float4*)(W + (size_t)(colBase + r) * K + k0 + c);
            Bs[c + 0][r] = b.x; Bs[c + 1][r] = b.y;
            Bs[c + 2][r] = b.z; Bs[c + 3][r] = b.w;
        }
        __syncthreads();

#pragma unroll
        for (int k = 0; k < BK; k++) {
            float ra[8], rb[8];
            const float4* pa = (const float4*)&As[k][ty * 8];
            const float4* pb = (const float4*)&Bs[k][tx * 8];
            float4 a0 = pa[0], a1 = pa[1];
            float4 b0 = pb[0], b1 = pb[1];
            ra[0] = a0.x; ra[1] = a0.y; ra[2] = a0.z; ra[3] = a0.w;
            ra[4] = a1.x; ra[5] = a1.y; ra[6] = a1.z; ra[7] = a1.w;
            rb[0] = b0.x; rb[1] = b0.y; rb[2] = b0.z; rb[3] = b0.w;
            rb[4] = b1.x; rb[5] = b1.y; rb[6] = b1.z; rb[7] = b1.w;
#pragma unroll
            for (int i = 0; i < 8; i++)
#pragma unroll
                for (int j = 0; j < 8; j++)
                    acc[i][j] = fmaf(ra[i], rb[j], acc[i][j]);
        }
        __syncthreads();
    }

    // Epilogue: vectorized stores (+ bias)
#pragma unroll
    for (int i = 0; i < 8; i++) {
        int row = rowBase + ty * 8 + i;
        float* crow = C + (size_t)row * N + colBase + tx * 8;
#pragma unroll
        for (int j4 = 0; j4 < 2; j4++) {
            float4 o;
            o.x = acc[i][j4 * 4 + 0];
            o.y = acc[i][j4 * 4 + 1];
            o.z = acc[i][j4 * 4 + 2];
            o.w = acc[i][j4 * 4 + 3];
            if (BIAS) {
                const float* brow = bias + colBase + tx * 8 + j4 * 4;
                o.x += brow[0]; o.y += brow[1]; o.z += brow[2]; o.w += brow[3];
            }
            *(float4*)(crow + j4 * 4) = o;
        }
    }
}

// ---------------------------------------------------------------------------
// Flash attention (fp32, causal), one (b, h, q-tile of 64) per block.
// Q/K/V/O are [B,S,H*HD] row-major; head h uses columns [h*64, h*64+64).
// 256 threads: 16x16 grid, each thread owns a 4x4 sub-tile of the 64x64
// score tile and a 4x4 sub-tile of the 64x64 output accumulator.
// Dynamic smem: 4 arrays of 64x65 floats = 66,560 bytes.
// ---------------------------------------------------------------------------
#define ATTN_SMEM (4 * 64 * 65 * 4)

__global__ __launch_bounds__(256) void attn_kernel(
    const float* __restrict__ Qg, const float* __restrict__ Kg,
    const float* __restrict__ Vg, float* __restrict__ Og)
{
    extern __shared__ float sm[];
    float (*sQ)[65] = (float(*)[65])(sm);
    float (*sK)[65] = (float(*)[65])(sm + 1 * 64 * 65);
    float (*sV)[65] = (float(*)[65])(sm + 2 * 64 * 65);
    float (*sP)[65] = (float(*)[65])(sm + 3 * 64 * 65);

    const int qt = blockIdx.x;       // q-tile index (0..31)
    const int h  = blockIdx.y;
    const int b  = blockIdx.z;
    const int tid = threadIdx.x;
    const int tx = tid & 15;         // score cols tx*4..+3
    const int ty = tid >> 4;         // score rows ty*4..+3

    const size_t headBase = ((size_t)b * NS) * ND + (size_t)h * NHD;
    const float scale = 0.125f;      // 1/sqrt(64)

    // Load Q tile (64 rows x 64 dims)
#pragma unroll
    for (int v = 0; v < 4; v++) {
        int f = tid + v * 256;       // float4 index 0..1023
        int r = f >> 4;              // 0..63
        int c = (f & 15) << 2;       // 0..60
        float4 q = *(const float4*)(Qg + headBase + (size_t)(qt * 64 + r) * ND + c);
        sQ[r][c] = q.x; sQ[r][c + 1] = q.y; sQ[r][c + 2] = q.z; sQ[r][c + 3] = q.w;
    }

    float m[4], l[4], acc[4][4];
#pragma unroll
    for (int i = 0; i < 4; i++) {
        m[i] = -1e30f; l[i] = 0.0f;
#pragma unroll
        for (int j = 0; j < 4; j++) acc[i][j] = 0.0f;
    }

    for (int jt = 0; jt <= qt; jt++) {
        // Load K and V tiles for this kv block
#pragma unroll
        for (int v = 0; v < 4; v++) {
            int f = tid + v * 256;
            int r = f >> 4;
            int c = (f & 15) << 2;
            size_t off = headBase + (size_t)(jt * 64 + r) * ND + c;
            float4 kk = *(const float4*)(Kg + off);
            sK[r][c] = kk.x; sK[r][c + 1] = kk.y; sK[r][c + 2] = kk.z; sK[r][c + 3] = kk.w;
            float4 vv = *(const float4*)(Vg + off);
            sV[r][c] = vv.x; sV[r][c + 1] = vv.y; sV[r][c + 2] = vv.z; sV[r][c + 3] = vv.w;
        }
        __syncthreads();

        // S = Q @ K^T  (4x4 per thread)
        float s[4][4];
#pragma unroll
        for (int i = 0; i < 4; i++)
#pragma unroll
            for (int j = 0; j < 4; j++) s[i][j] = 0.0f;

#pragma unroll
        for (int d = 0; d < 64; d++) {
            float qv[4], kv[4];
#pragma unroll
            for (int i = 0; i < 4; i++) qv[i] = sQ[ty * 4 + i][d];
#pragma unroll
            for (int j = 0; j < 4; j++) kv[j] = sK[tx * 4 + j][d];
#pragma unroll
            for (int i = 0; i < 4; i++)
#pragma unroll
                for (int j = 0; j < 4; j++)
                    s[i][j] = fmaf(qv[i], kv[j], s[i][j]);
        }

        // scale + causal mask (only the diagonal tile needs masking)
#pragma unroll
        for (int i = 0; i < 4; i++)
#pragma unroll
            for (int j = 0; j < 4; j++) {
                s[i][j] *= scale;
                if (jt == qt && (tx * 4 + j) > (ty * 4 + i)) s[i][j] = -1e30f;
            }

        // online softmax: per-row reduce over 16 tx-threads (lane bits 0..3)
#pragma unroll
        for (int i = 0; i < 4; i++) {
            float mt = s[i][0];
#pragma unroll
            for (int j = 1; j < 4; j++) mt = fmaxf(mt, s[i][j]);
#pragma unroll
            for (int off = 8; off >= 1; off >>= 1)
                mt = fmaxf(mt, __shfl_xor_sync(0xffffffffu, mt, off));
            float mn = fmaxf(m[i], mt);
            float corr = __expf(m[i] - mn);
            l[i] *= corr;
#pragma unroll
            for (int j = 0; j < 4; j++) acc[i][j] *= corr;
            float ps = 0.0f;
#pragma unroll
            for (int j = 0; j < 4; j++) {
                float p = __expf(s[i][j] - mn);
                s[i][j] = p;
                ps += p;
            }
#pragma unroll
            for (int off = 8; off >= 1; off >>= 1)
                ps += __shfl_xor_sync(0xffffffffu, ps, off);
            l[i] += ps;
            m[i] = mn;
        }

        // stage P, then acc += P @ V
#pragma unroll
        for (int i = 0; i < 4; i++)
#pragma unroll
            for (int j = 0; j < 4; j++) sP[ty * 4 + i][tx * 4 + j] = s[i][j];
        __syncthreads();

#pragma unroll
        for (int k = 0; k < 64; k++) {
            float pv[4], vv[4];
#pragma unroll
            for (int i = 0; i < 4; i++) pv[i] = sP[ty * 4 + i][k];
#pragma unroll
            for (int j = 0; j < 4; j++) vv[j] = sV[k][tx * 4 + j];
#pragma unroll
            for (int i = 0; i < 4; i++)
#pragma unroll
                for (int j = 0; j < 4; j++)
                    acc[i][j] = fmaf(pv[i], vv[j], acc[i][j]);
        }
        __syncthreads();   // protect sK/sV/sP before next iteration's loads
    }

    // epilogue: normalize and write context
#pragma unroll
    for (int i = 0; i < 4; i++) {
        float inv = 1.0f / l[i];
        int row = qt * 64 + ty * 4 + i;
        float* orow = Og + headBase + (size_t)row * ND + tx * 4;
#pragma unroll
        for (int j = 0; j < 4; j++) orow[j] = acc[i][j] * inv;
    }
}

// ---------------------------------------------------------------------------
// Launch
// inputs (metadata order): x, W_q, W_k, W_v, W_o, b_o ; output fp32 [B,S,D]
// ---------------------------------------------------------------------------
extern "C" void kernel_launch(void* const* d_in, const int* in_sizes, int n_in,
                              void* d_out, int out_size)
{
    const float* x  = (const float*)d_in[0];
    const float* Wq = (const float*)d_in[1];
    const float* Wk = (const float*)d_in[2];
    const float* Wv = (const float*)d_in[3];
    const float* Wo = (const float*)d_in[4];
    const float* bo = (const float*)d_in[5];
    float* out = (float*)d_out;

    float *Qp, *Kp, *Vp, *Cp;
    cudaGetSymbolAddress((void**)&Qp, g_Q);
    cudaGetSymbolAddress((void**)&Kp, g_K);
    cudaGetSymbolAddress((void**)&Vp, g_V);
    cudaGetSymbolAddress((void**)&Cp, g_C);

    // one-time (idempotent) opt-in for >48KB dynamic smem
    cudaFuncSetAttribute(attn_kernel,
                         cudaFuncAttributeMaxDynamicSharedMemorySize, ATTN_SMEM);

    dim3 gGemm(ND / 128, MTOT / 128);

    gemm_nt<false><<<gGemm, 256>>>(x, Wq, nullptr, Qp, MTOT, ND, ND);
    gemm_nt<false><<<gGemm, 256>>>(x, Wk, nullptr, Kp, MTOT, ND, ND);
    gemm_nt<false><<<gGemm, 256>>>(x, Wv, nullptr, Vp, MTOT, ND, ND);

    dim3 gAttn(NS / 64, NH, NB);
    attn_kernel<<<gAttn, 256, ATTN_SMEM>>>(Qp, Kp, Vp, Cp);

    gemm_nt<true><<<gGemm, 256>>>(Cp, Wo, bo, out, MTOT, ND, ND);
}

// round 3
// speedup vs baseline: 1.6723x; 1.6723x over previous
#include <cuda_runtime.h>
#include <math.h>
#include <cstdint>

// Problem dims (fixed by reference)
#define NB 4
#define NS 2048
#define ND 1024
#define NH 16
#define NHD 64
#define MTOT (NB * NS)   // 8192 rows for the projection GEMMs

// ---------------------------------------------------------------------------
// Scratch (device-global: no cudaMalloc allowed anywhere)
// ---------------------------------------------------------------------------
__device__ float g_Q[NB * NS * ND];
__device__ float g_K[NB * NS * ND];
__device__ float g_V[NB * NS * ND];
__device__ float g_C[NB * NS * ND];

// ---------------------------------------------------------------------------
// tf32 mma.sync GEMM (NT):  C[m,n] = sum_k A[m,k] * W[n,k]  (+ optional bias)
//
// CTA tile 128x128, BK=32, 256 threads = 8 warps in a 2(m) x 4(n) grid;
// each warp owns a 64x32 tile = 4x4 grid of m16n8k8 tf32 MMAs per k-chunk(8).
//
// SMEM holds fragment-packed tiles so the mainloop does only vector LDS:
//   A: [mt 0..7][kc 0..3][lane 0..31][reg 0..3]  (+4 float pad per block)
//   B: [nt 0..15][kc 0..3][lane 0..31][reg 0..1] (+4 float pad per block)
// Fragment mappings (PTX m16n8k8.row.col):
//   A elem (m,k): lane=(m%8)*4+(k%4), reg=((m%16)/8) + 2*((k%8)/4)
//   B elem (n,k): lane=(n%8)*4+(k%4), reg=(k%8)/4
//   C elem: row=lane/4 (+8 for c2,c3), col=2*(lane%4)+(0,1)
// ---------------------------------------------------------------------------
#define A_BLK 132                       // 128 + 4 pad floats per (mt,kc) block
#define B_BLK 68                        // 64 + 4 pad
#define A_FLOATS (8 * 4 * A_BLK)        // 4224
#define B_FLOATS (16 * 4 * B_BLK)       // 4352
#define BUF_FLOATS (A_FLOATS + B_FLOATS)  // 8576
#define GEMM_SMEM (2 * BUF_FLOATS * 4)    // 68608 B

__device__ __forceinline__ void mma_tf32(
    float& d0, float& d1, float& d2, float& d3,
    uint32_t a0, uint32_t a1, uint32_t a2, uint32_t a3,
    uint32_t b0, uint32_t b1)
{
    asm volatile(
        "mma.sync.aligned.m16n8k8.row.col.f32.tf32.tf32.f32 "
        "{%0,%1,%2,%3}, {%4,%5,%6,%7}, {%8,%9}, {%0,%1,%2,%3};"
        : "+f"(d0), "+f"(d1), "+f"(d2), "+f"(d3)
        : "r"(a0), "r"(a1), "r"(a2), "r"(a3), "r"(b0), "r"(b1));
}

__device__ __forceinline__ uint32_t f2tf32(float x) {
    uint32_t r;
    asm("cvt.rna.tf32.f32 %0, %1;" : "=r"(r) : "f"(x));
    return r;
}

// Load one 128x32 chunk of A and W into registers (tf32-rounded).
__device__ __forceinline__ void load_chunk(
    const float* __restrict__ A, const float* __restrict__ W,
    int K, int rowBase, int colBase, int k0, int tid,
    uint32_t ar[16], uint32_t br[16])
{
#pragma unroll
    for (int v = 0; v < 4; v++) {
        int f = tid + v * 256;          // float4 idx 0..1023
        int r = f >> 3;                 // tile row 0..127
        int c = (f & 7) << 2;           // k offset 0..28
        float4 a = *(const float4*)(A + (size_t)(rowBase + r) * K + k0 + c);
        float4 w = *(const float4*)(W + (size_t)(colBase + r) * K + k0 + c);
        ar[v * 4 + 0] = f2tf32(a.x); ar[v * 4 + 1] = f2tf32(a.y);
        ar[v * 4 + 2] = f2tf32(a.z); ar[v * 4 + 3] = f2tf32(a.w);
        br[v * 4 + 0] = f2tf32(w.x); br[v * 4 + 1] = f2tf32(w.y);
        br[v * 4 + 2] = f2tf32(w.z); br[v * 4 + 3] = f2tf32(w.w);
    }
}

// Scatter registers into fragment-packed SMEM.
__device__ __forceinline__ void store_chunk(
    uint32_t* __restrict__ sA, uint32_t* __restrict__ sB,
    int tid, const uint32_t ar[16], const uint32_t br[16])
{
#pragma unroll
    for (int v = 0; v < 4; v++) {
        int f = tid + v * 256;
        int r = f >> 3;
        int c = (f & 7) << 2;
        int mt = r >> 4;
        int nt = r >> 3;
        int kc = c >> 3;
        int regA = ((r >> 3) & 1) | (((c >> 2) & 1) << 1);
        int regB = (c >> 2) & 1;
        int laneBase = (r & 7) * 4;
#pragma unroll
        for (int i = 0; i < 4; i++) {
            int lane = laneBase + i;
            sA[(mt * 4 + kc) * A_BLK + lane * 4 + regA] = ar[v * 4 + i];
            sB[(nt * 4 + kc) * B_BLK + lane * 2 + regB] = br[v * 4 + i];
        }
    }
}

template <bool BIAS>
__global__ __launch_bounds__(256) void gemm_mma(
    const float* __restrict__ A, const float* __restrict__ W,
    const float* __restrict__ bias, float* __restrict__ C, int K)
{
    extern __shared__ uint32_t smu[];

    const int tid = threadIdx.x;
    const int wid = tid >> 5;
    const int lane = tid & 31;
    const int wm = wid >> 2;            // 0..1 -> m offset wm*64
    const int wn = wid & 3;             // 0..3 -> n offset wn*32
    const int rowBase = blockIdx.y * 128;
    const int colBase = blockIdx.x * 128;

    float acc[4][4][4];
#pragma unroll
    for (int i = 0; i < 4; i++)
#pragma unroll
        for (int j = 0; j < 4; j++)
#pragma unroll
            for (int k = 0; k < 4; k++) acc[i][j][k] = 0.0f;

    const int NCH = K / 32;
    uint32_t ar[16], br[16];

    // prologue: stage chunk 0
    load_chunk(A, W, K, rowBase, colBase, 0, tid, ar, br);
    store_chunk(smu, smu + A_FLOATS, tid, ar, br);
    __syncthreads();

    for (int c = 0; c < NCH; c++) {
        const int buf = c & 1;
        uint32_t* sA = smu + buf * BUF_FLOATS;
        uint32_t* sB = sA + A_FLOATS;

        if (c + 1 < NCH)
            load_chunk(A, W, K, rowBase, colBase, (c + 1) * 32, tid, ar, br);

#pragma unroll
        for (int kc = 0; kc < 4; kc++) {
            uint32_t af[4][4], bf[4][2];
#pragma unroll
            for (int mtl = 0; mtl < 4; mtl++) {
                int mt = wm * 4 + mtl;
                const uint4 va = *(const uint4*)(sA + (mt * 4 + kc) * A_BLK + lane * 4);
                af[mtl][0] = va.x; af[mtl][1] = va.y;
                af[mtl][2] = va.z; af[mtl][3] = va.w;
            }
#pragma unroll
            for (int ntl = 0; ntl < 4; ntl++) {
                int nt = wn * 4 + ntl;
                const uint2 vb = *(const uint2*)(sB + (nt * 4 + kc) * B_BLK + lane * 2);
                bf[ntl][0] = vb.x; bf[ntl][1] = vb.y;
            }
#pragma unroll
            for (int mtl = 0; mtl < 4; mtl++)
#pragma unroll
                for (int ntl = 0; ntl < 4; ntl++)
                    mma_tf32(acc[mtl][ntl][0], acc[mtl][ntl][1],
                             acc[mtl][ntl][2], acc[mtl][ntl][3],
                             af[mtl][0], af[mtl][1], af[mtl][2], af[mtl][3],
                             bf[ntl][0], bf[ntl][1]);
        }

        if (c + 1 < NCH) {
            uint32_t* dA = smu + (buf ^ 1) * BUF_FLOATS;
            store_chunk(dA, dA + A_FLOATS, tid, ar, br);
        }
        __syncthreads();
    }

    // epilogue: write C (+bias); c-frag: row=lane/4(+8), col=2*(lane%4)(+1)
    const int rql = lane >> 2;
    const int cql = (lane & 3) * 2;
#pragma unroll
    for (int mtl = 0; mtl < 4; mtl++) {
        int m0 = rowBase + wm * 64 + mtl * 16 + rql;
#pragma unroll
        for (int ntl = 0; ntl < 4; ntl++) {
            int n0 = colBase + wn * 32 + ntl * 8 + cql;
            float b0 = 0.f, b1 = 0.f;
            if (BIAS) { b0 = bias[n0]; b1 = bias[n0 + 1]; }
            float2 lo = make_float2(acc[mtl][ntl][0] + b0, acc[mtl][ntl][1] + b1);
            float2 hi = make_float2(acc[mtl][ntl][2] + b0, acc[mtl][ntl][3] + b1);
            *(float2*)(C + (size_t)m0 * ND + n0) = lo;
            *(float2*)(C + (size_t)(m0 + 8) * ND + n0) = hi;
        }
    }
}

// ---------------------------------------------------------------------------
// Flash attention (fp32, causal) — unchanged (validated R1).
// ---------------------------------------------------------------------------
#define ATTN_SMEM (4 * 64 * 65 * 4)

__global__ __launch_bounds__(256) void attn_kernel(
    const float* __restrict__ Qg, const float* __restrict__ Kg,
    const float* __restrict__ Vg, float* __restrict__ Og)
{
    extern __shared__ float sm[];
    float (*sQ)[65] = (float(*)[65])(sm);
    float (*sK)[65] = (float(*)[65])(sm + 1 * 64 * 65);
    float (*sV)[65] = (float(*)[65])(sm + 2 * 64 * 65);
    float (*sP)[65] = (float(*)[65])(sm + 3 * 64 * 65);

    const int qt = blockIdx.x;
    const int h  = blockIdx.y;
    const int b  = blockIdx.z;
    const int tid = threadIdx.x;
    const int tx = tid & 15;
    const int ty = tid >> 4;

    const size_t headBase = ((size_t)b * NS) * ND + (size_t)h * NHD;
    const float scale = 0.125f;

#pragma unroll
    for (int v = 0; v < 4; v++) {
        int f = tid + v * 256;
        int r = f >> 4;
        int c = (f & 15) << 2;
        float4 q = *(const float4*)(Qg + headBase + (size_t)(qt * 64 + r) * ND + c);
        sQ[r][c] = q.x; sQ[r][c + 1] = q.y; sQ[r][c + 2] = q.z; sQ[r][c + 3] = q.w;
    }

    float m[4], l[4], acc[4][4];
#pragma unroll
    for (int i = 0; i < 4; i++) {
        m[i] = -1e30f; l[i] = 0.0f;
#pragma unroll
        for (int j = 0; j < 4; j++) acc[i][j] = 0.0f;
    }

    for (int jt = 0; jt <= qt; jt++) {
#pragma unroll
        for (int v = 0; v < 4; v++) {
            int f = tid + v * 256;
            int r = f >> 4;
            int c = (f & 15) << 2;
            size_t off = headBase + (size_t)(jt * 64 + r) * ND + c;
            float4 kk = *(const float4*)(Kg + off);
            sK[r][c] = kk.x; sK[r][c + 1] = kk.y; sK[r][c + 2] = kk.z; sK[r][c + 3] = kk.w;
            float4 vv = *(const float4*)(Vg + off);
            sV[r][c] = vv.x; sV[r][c + 1] = vv.y; sV[r][c + 2] = vv.z; sV[r][c + 3] = vv.w;
        }
        __syncthreads();

        float s[4][4];
#pragma unroll
        for (int i = 0; i < 4; i++)
#pragma unroll
            for (int j = 0; j < 4; j++) s[i][j] = 0.0f;

#pragma unroll
        for (int d = 0; d < 64; d++) {
            float qv[4], kv[4];
#pragma unroll
            for (int i = 0; i < 4; i++) qv[i] = sQ[ty * 4 + i][d];
#pragma unroll
            for (int j = 0; j < 4; j++) kv[j] = sK[tx * 4 + j][d];
#pragma unroll
            for (int i = 0; i < 4; i++)
#pragma unroll
                for (int j = 0; j < 4; j++)
                    s[i][j] = fmaf(qv[i], kv[j], s[i][j]);
        }

#pragma unroll
        for (int i = 0; i < 4; i++)
#pragma unroll
            for (int j = 0; j < 4; j++) {
                s[i][j] *= scale;
                if (jt == qt && (tx * 4 + j) > (ty * 4 + i)) s[i][j] = -1e30f;
            }

#pragma unroll
        for (int i = 0; i < 4; i++) {
            float mt = s[i][0];
#pragma unroll
            for (int j = 1; j < 4; j++) mt = fmaxf(mt, s[i][j]);
#pragma unroll
            for (int off = 8; off >= 1; off >>= 1)
                mt = fmaxf(mt, __shfl_xor_sync(0xffffffffu, mt, off));
            float mn = fmaxf(m[i], mt);
            float corr = __expf(m[i] - mn);
            l[i] *= corr;
#pragma unroll
            for (int j = 0; j < 4; j++) acc[i][j] *= corr;
            float ps = 0.0f;
#pragma unroll
            for (int j = 0; j < 4; j++) {
                float p = __expf(s[i][j] - mn);
                s[i][j] = p;
                ps += p;
            }
#pragma unroll
            for (int off = 8; off >= 1; off >>= 1)
                ps += __shfl_xor_sync(0xffffffffu, ps, off);
            l[i] += ps;
            m[i] = mn;
        }

#pragma unroll
        for (int i = 0; i < 4; i++)
#pragma unroll
            for (int j = 0; j < 4; j++) sP[ty * 4 + i][tx * 4 + j] = s[i][j];
        __syncthreads();

#pragma unroll
        for (int k = 0; k < 64; k++) {
            float pv[4], vv[4];
#pragma unroll
            for (int i = 0; i < 4; i++) pv[i] = sP[ty * 4 + i][k];
#pragma unroll
            for (int j = 0; j < 4; j++) vv[j] = sV[k][tx * 4 + j];
#pragma unroll
            for (int i = 0; i < 4; i++)
#pragma unroll
                for (int j = 0; j < 4; j++)
                    acc[i][j] = fmaf(pv[i], vv[j], acc[i][j]);
        }
        __syncthreads();
    }

#pragma unroll
    for (int i = 0; i < 4; i++) {
        float inv = 1.0f / l[i];
        int row = qt * 64 + ty * 4 + i;
        float* orow = Og + headBase + (size_t)row * ND + tx * 4;
#pragma unroll
        for (int j = 0; j < 4; j++) orow[j] = acc[i][j] * inv;
    }
}

// ---------------------------------------------------------------------------
// Launch:  inputs (metadata order): x, W_q, W_k, W_v, W_o, b_o ; out fp32
// ---------------------------------------------------------------------------
extern "C" void kernel_launch(void* const* d_in, const int* in_sizes, int n_in,
                              void* d_out, int out_size)
{
    const float* x  = (const float*)d_in[0];
    const float* Wq = (const float*)d_in[1];
    const float* Wk = (const float*)d_in[2];
    const float* Wv = (const float*)d_in[3];
    const float* Wo = (const float*)d_in[4];
    const float* bo = (const float*)d_in[5];
    float* out = (float*)d_out;

    float *Qp, *Kp, *Vp, *Cp;
    cudaGetSymbolAddress((void**)&Qp, g_Q);
    cudaGetSymbolAddress((void**)&Kp, g_K);
    cudaGetSymbolAddress((void**)&Vp, g_V);
    cudaGetSymbolAddress((void**)&Cp, g_C);

    cudaFuncSetAttribute(attn_kernel,
                         cudaFuncAttributeMaxDynamicSharedMemorySize, ATTN_SMEM);
    cudaFuncSetAttribute(gemm_mma<false>,
                         cudaFuncAttributeMaxDynamicSharedMemorySize, GEMM_SMEM);
    cudaFuncSetAttribute(gemm_mma<true>,
                         cudaFuncAttributeMaxDynamicSharedMemorySize, GEMM_SMEM);

    dim3 gGemm(ND / 128, MTOT / 128);

    gemm_mma<false><<<gGemm, 256, GEMM_SMEM>>>(x, Wq, nullptr, Qp, ND);
    gemm_mma<false><<<gGemm, 256, GEMM_SMEM>>>(x, Wk, nullptr, Kp, ND);
    gemm_mma<false><<<gGemm, 256, GEMM_SMEM>>>(x, Wv, nullptr, Vp, ND);

    dim3 gAttn(NS / 64, NH, NB);
    attn_kernel<<<gAttn, 256, ATTN_SMEM>>>(Qp, Kp, Vp, Cp);

    gemm_mma<true><<<gGemm, 256, GEMM_SMEM>>>(Cp, Wo, bo, out, ND);
}

// round 6
// speedup vs baseline: 2.9043x; 1.7368x over previous
#include <cuda_runtime.h>
#include <math.h>
#include <cstdint>

// Problem dims (fixed by reference)
#define NB 4
#define NS 2048
#define ND 1024
#define NH 16
#define NHD 64
#define MTOT (NB * NS)   // 8192 rows for the projection GEMMs

// ---------------------------------------------------------------------------
// Scratch (device-global: no cudaMalloc allowed anywhere)
// ---------------------------------------------------------------------------
__device__ float g_Q[NB * NS * ND];
__device__ float g_K[NB * NS * ND];
__device__ float g_V[NB * NS * ND];
__device__ float g_C[NB * NS * ND];

// ---------------------------------------------------------------------------
// Shared helpers
// ---------------------------------------------------------------------------
__device__ __forceinline__ void mma_tf32(
    float& d0, float& d1, float& d2, float& d3,
    uint32_t a0, uint32_t a1, uint32_t a2, uint32_t a3,
    uint32_t b0, uint32_t b1)
{
    asm volatile(
        "mma.sync.aligned.m16n8k8.row.col.f32.tf32.tf32.f32 "
        "{%0,%1,%2,%3}, {%4,%5,%6,%7}, {%8,%9}, {%0,%1,%2,%3};"
        : "+f"(d0), "+f"(d1), "+f"(d2), "+f"(d3)
        : "r"(a0), "r"(a1), "r"(a2), "r"(a3), "r"(b0), "r"(b1));
}

__device__ __forceinline__ uint32_t f2tf32(float x) {
    uint32_t r;
    asm("cvt.rna.tf32.f32 %0, %1;" : "=r"(r) : "f"(x));
    return r;
}

// ---------------------------------------------------------------------------
// tf32 mma.sync GEMM (NT) — unchanged from R3 (validated).
// CTA tile 128x128, BK=32, 256 threads = 8 warps (2m x 4n), 64x32 per warp.
// ---------------------------------------------------------------------------
#define A_BLK 132
#define B_BLK 68
#define A_FLOATS (8 * 4 * A_BLK)
#define B_FLOATS (16 * 4 * B_BLK)
#define BUF_FLOATS (A_FLOATS + B_FLOATS)
#define GEMM_SMEM (2 * BUF_FLOATS * 4)

__device__ __forceinline__ void load_chunk(
    const float* __restrict__ A, const float* __restrict__ W,
    int K, int rowBase, int colBase, int k0, int tid,
    uint32_t ar[16], uint32_t br[16])
{
#pragma unroll
    for (int v = 0; v < 4; v++) {
        int f = tid + v * 256;
        int r = f >> 3;
        int c = (f & 7) << 2;
        float4 a = *(const float4*)(A + (size_t)(rowBase + r) * K + k0 + c);
        float4 w = *(const float4*)(W + (size_t)(colBase + r) * K + k0 + c);
        ar[v * 4 + 0] = f2tf32(a.x); ar[v * 4 + 1] = f2tf32(a.y);
        ar[v * 4 + 2] = f2tf32(a.z); ar[v * 4 + 3] = f2tf32(a.w);
        br[v * 4 + 0] = f2tf32(w.x); br[v * 4 + 1] = f2tf32(w.y);
        br[v * 4 + 2] = f2tf32(w.z); br[v * 4 + 3] = f2tf32(w.w);
    }
}

__device__ __forceinline__ void store_chunk(
    uint32_t* __restrict__ sA, uint32_t* __restrict__ sB,
    int tid, const uint32_t ar[16], const uint32_t br[16])
{
#pragma unroll
    for (int v = 0; v < 4; v++) {
        int f = tid + v * 256;
        int r = f >> 3;
        int c = (f & 7) << 2;
        int mt = r >> 4;
        int nt = r >> 3;
        int kc = c >> 3;
        int regA = ((r >> 3) & 1) | (((c >> 2) & 1) << 1);
        int regB = (c >> 2) & 1;
        int laneBase = (r & 7) * 4;
#pragma unroll
        for (int i = 0; i < 4; i++) {
            int lane = laneBase + i;
            sA[(mt * 4 + kc) * A_BLK + lane * 4 + regA] = ar[v * 4 + i];
            sB[(nt * 4 + kc) * B_BLK + lane * 2 + regB] = br[v * 4 + i];
        }
    }
}

template <bool BIAS>
__global__ __launch_bounds__(256) void gemm_mma(
    const float* __restrict__ A, const float* __restrict__ W,
    const float* __restrict__ bias, float* __restrict__ C, int K)
{
    extern __shared__ uint32_t smu[];

    const int tid = threadIdx.x;
    const int wid = tid >> 5;
    const int lane = tid & 31;
    const int wm = wid >> 2;
    const int wn = wid & 3;
    const int rowBase = blockIdx.y * 128;
    const int colBase = blockIdx.x * 128;

    float acc[4][4][4];
#pragma unroll
    for (int i = 0; i < 4; i++)
#pragma unroll
        for (int j = 0; j < 4; j++)
#pragma unroll
            for (int k = 0; k < 4; k++) acc[i][j][k] = 0.0f;

    const int NCH = K / 32;
    uint32_t ar[16], br[16];

    load_chunk(A, W, K, rowBase, colBase, 0, tid, ar, br);
    store_chunk(smu, smu + A_FLOATS, tid, ar, br);
    __syncthreads();

    for (int c = 0; c < NCH; c++) {
        const int buf = c & 1;
        uint32_t* sA = smu + buf * BUF_FLOATS;
        uint32_t* sB = sA + A_FLOATS;

        if (c + 1 < NCH)
            load_chunk(A, W, K, rowBase, colBase, (c + 1) * 32, tid, ar, br);

#pragma unroll
        for (int kc = 0; kc < 4; kc++) {
            uint32_t af[4][4], bf[4][2];
#pragma unroll
            for (int mtl = 0; mtl < 4; mtl++) {
                int mt = wm * 4 + mtl;
                const uint4 va = *(const uint4*)(sA + (mt * 4 + kc) * A_BLK + lane * 4);
                af[mtl][0] = va.x; af[mtl][1] = va.y;
                af[mtl][2] = va.z; af[mtl][3] = va.w;
            }
#pragma unroll
            for (int ntl = 0; ntl < 4; ntl++) {
                int nt = wn * 4 + ntl;
                const uint2 vb = *(const uint2*)(sB + (nt * 4 + kc) * B_BLK + lane * 2);
                bf[ntl][0] = vb.x; bf[ntl][1] = vb.y;
            }
#pragma unroll
            for (int mtl = 0; mtl < 4; mtl++)
#pragma unroll
                for (int ntl = 0; ntl < 4; ntl++)
                    mma_tf32(acc[mtl][ntl][0], acc[mtl][ntl][1],
                             acc[mtl][ntl][2], acc[mtl][ntl][3],
                             af[mtl][0], af[mtl][1], af[mtl][2], af[mtl][3],
                             bf[ntl][0], bf[ntl][1]);
        }

        if (c + 1 < NCH) {
            uint32_t* dA = smu + (buf ^ 1) * BUF_FLOATS;
            store_chunk(dA, dA + A_FLOATS, tid, ar, br);
        }
        __syncthreads();
    }

    const int rql = lane >> 2;
    const int cql = (lane & 3) * 2;
#pragma unroll
    for (int mtl = 0; mtl < 4; mtl++) {
        int m0 = rowBase + wm * 64 + mtl * 16 + rql;
#pragma unroll
        for (int ntl = 0; ntl < 4; ntl++) {
            int n0 = colBase + wn * 32 + ntl * 8 + cql;
            float b0 = 0.f, b1 = 0.f;
            if (BIAS) { b0 = bias[n0]; b1 = bias[n0 + 1]; }
            float2 lo = make_float2(acc[mtl][ntl][0] + b0, acc[mtl][ntl][1] + b1);
            float2 hi = make_float2(acc[mtl][ntl][2] + b0, acc[mtl][ntl][3] + b1);
            *(float2*)(C + (size_t)m0 * ND + n0) = lo;
            *(float2*)(C + (size_t)(m0 + 8) * ND + n0) = hi;
        }
    }
}

// ---------------------------------------------------------------------------
// Tensor-core flash attention (tf32 mma.sync, fp32 softmax, causal).
// CTA = 64 q-rows x one (b,h). 4 warps (128 thr), 16 q-rows per warp.
// kv processed in blocks of 64.
//
// SMEM (u32 tf32, pitch 68 words): sQ[64], sK[64], sV[64], sP[4 warps x 16].
// Fragment maps (m16n8k8 tf32, validated by R3 GEMM):
//   A(row g=lane>>2): a0=(g, q4) a1=(g+8, q4) a2=(g, q4+4) a3=(g+8, q4+4)
//   B: b0=(n=g, k=q4), b1=(n=g, k=q4+4)
//   C: c0=(g, 2*q4) c1=(g, 2*q4+1) c2/c3 = rows g+8
// ---------------------------------------------------------------------------
#define AT_PITCH 68
#define AT_SMEM (4 * 64 * AT_PITCH * 4)   // 69,632 B

__global__ __launch_bounds__(128) void attn_mma(
    const float* __restrict__ Qg, const float* __restrict__ Kg,
    const float* __restrict__ Vg, float* __restrict__ Og)
{
    extern __shared__ uint32_t su[];
    uint32_t* sQ = su;
    uint32_t* sK = sQ + 64 * AT_PITCH;
    uint32_t* sV = sK + 64 * AT_PITCH;
    uint32_t* sP = sV + 64 * AT_PITCH;

    const int qt = blockIdx.x;
    const int h  = blockIdx.y;
    const int b  = blockIdx.z;
    const int tid  = threadIdx.x;
    const int wid  = tid >> 5;
    const int lane = tid & 31;
    const int g    = lane >> 2;
    const int q4   = lane & 3;
    const size_t headBase = ((size_t)b * NS) * ND + (size_t)h * NHD;

    // Load Q tile (64 x 64) -> tf32 smem
#pragma unroll
    for (int v = 0; v < 8; v++) {
        int f = tid + v * 128;
        int r = f >> 4;
        int c = (f & 15) << 2;
        float4 q = *(const float4*)(Qg + headBase + (size_t)(qt * 64 + r) * ND + c);
        uint4 t;
        t.x = f2tf32(q.x); t.y = f2tf32(q.y); t.z = f2tf32(q.z); t.w = f2tf32(q.w);
        *(uint4*)(sQ + r * AT_PITCH + c) = t;
    }

    float m0 = -1e30f, m1 = -1e30f, l0 = 0.0f, l1 = 0.0f;
    float ctx[8][4];
#pragma unroll
    for (int nt = 0; nt < 8; nt++)
#pragma unroll
        for (int e = 0; e < 4; e++) ctx[nt][e] = 0.0f;

    const int rowW = wid * 16;                 // warp's q-row base (CTA-local)
    uint32_t* sPw = sP + wid * 16 * AT_PITCH;  // warp-private P staging

    for (int jt = 0; jt <= qt; jt++) {
        // Stage K,V block (64 x 64) -> tf32 smem
#pragma unroll
        for (int v = 0; v < 8; v++) {
            int f = tid + v * 128;
            int r = f >> 4;
            int c = (f & 15) << 2;
            size_t off = headBase + (size_t)(jt * 64 + r) * ND + c;
            float4 kk = *(const float4*)(Kg + off);
            float4 vv = *(const float4*)(Vg + off);
            uint4 tk, tv;
            tk.x = f2tf32(kk.x); tk.y = f2tf32(kk.y); tk.z = f2tf32(kk.z); tk.w = f2tf32(kk.w);
            tv.x = f2tf32(vv.x); tv.y = f2tf32(vv.y); tv.z = f2tf32(vv.z); tv.w = f2tf32(vv.w);
            *(uint4*)(sK + r * AT_PITCH + c) = tk;
            *(uint4*)(sV + r * AT_PITCH + c) = tv;
        }
        __syncthreads();

        // S = Q @ K^T : 8 kc x 8 nt MMAs
        float s[8][4];
#pragma unroll
        for (int nt = 0; nt < 8; nt++)
#pragma unroll
            for (int e = 0; e < 4; e++) s[nt][e] = 0.0f;

#pragma unroll
        for (int kc = 0; kc < 8; kc++) {
            uint32_t a0 = sQ[(rowW + g)     * AT_PITCH + kc * 8 + q4];
            uint32_t a1 = sQ[(rowW + g + 8) * AT_PITCH + kc * 8 + q4];
            uint32_t a2 = sQ[(rowW + g)     * AT_PITCH + kc * 8 + q4 + 4];
            uint32_t a3 = sQ[(rowW + g + 8) * AT_PITCH + kc * 8 + q4 + 4];
#pragma unroll
            for (int nt = 0; nt < 8; nt++) {
                uint32_t b0 = sK[(nt * 8 + g) * AT_PITCH + kc * 8 + q4];
                uint32_t b1 = sK[(nt * 8 + g) * AT_PITCH + kc * 8 + q4 + 4];
                mma_tf32(s[nt][0], s[nt][1], s[nt][2], s[nt][3],
                         a0, a1, a2, a3, b0, b1);
            }
        }

        // scale + causal mask (diagonal block only)
#pragma unroll
        for (int nt = 0; nt < 8; nt++)
#pragma unroll
            for (int e = 0; e < 4; e++) s[nt][e] *= 0.125f;

        if (jt == qt) {
            int r0 = rowW + g, r1 = r0 + 8;
#pragma unroll
            for (int nt = 0; nt < 8; nt++) {
                int c0 = nt * 8 + 2 * q4;
                if (c0     > r0) s[nt][0] = -1e30f;
                if (c0 + 1 > r0) s[nt][1] = -1e30f;
                if (c0     > r1) s[nt][2] = -1e30f;
                if (c0 + 1 > r1) s[nt][3] = -1e30f;
            }
        }

        // online softmax (rows g and g+8; quad holds the row)
        float mx0 = -1e30f, mx1 = -1e30f;
#pragma unroll
        for (int nt = 0; nt < 8; nt++) {
            mx0 = fmaxf(mx0, fmaxf(s[nt][0], s[nt][1]));
            mx1 = fmaxf(mx1, fmaxf(s[nt][2], s[nt][3]));
        }
        mx0 = fmaxf(mx0, __shfl_xor_sync(0xffffffffu, mx0, 1));
        mx0 = fmaxf(mx0, __shfl_xor_sync(0xffffffffu, mx0, 2));
        mx1 = fmaxf(mx1, __shfl_xor_sync(0xffffffffu, mx1, 1));
        mx1 = fmaxf(mx1, __shfl_xor_sync(0xffffffffu, mx1, 2));

        float mn0 = fmaxf(m0, mx0), mn1 = fmaxf(m1, mx1);
        float cor0 = __expf(m0 - mn0), cor1 = __expf(m1 - mn1);
        l0 *= cor0; l1 *= cor1;
#pragma unroll
        for (int nt = 0; nt < 8; nt++) {
            ctx[nt][0] *= cor0; ctx[nt][1] *= cor0;
            ctx[nt][2] *= cor1; ctx[nt][3] *= cor1;
        }
        float sum0 = 0.0f, sum1 = 0.0f;
#pragma unroll
        for (int nt = 0; nt < 8; nt++) {
            float p0 = __expf(s[nt][0] - mn0);
            float p1 = __expf(s[nt][1] - mn0);
            float p2 = __expf(s[nt][2] - mn1);
            float p3 = __expf(s[nt][3] - mn1);
            s[nt][0] = p0; s[nt][1] = p1; s[nt][2] = p2; s[nt][3] = p3;
            sum0 += p0 + p1; sum1 += p2 + p3;
        }
        sum0 += __shfl_xor_sync(0xffffffffu, sum0, 1);
        sum0 += __shfl_xor_sync(0xffffffffu, sum0, 2);
        sum1 += __shfl_xor_sync(0xffffffffu, sum1, 1);
        sum1 += __shfl_xor_sync(0xffffffffu, sum1, 2);
        l0 += sum0; l1 += sum1;
        m0 = mn0; m1 = mn1;

        // stage P (tf32) into warp-private smem: c-frag -> row-major
#pragma unroll
        for (int nt = 0; nt < 8; nt++) {
            uint2 lo = make_uint2(f2tf32(s[nt][0]), f2tf32(s[nt][1]));
            uint2 hi = make_uint2(f2tf32(s[nt][2]), f2tf32(s[nt][3]));
            *(uint2*)(sPw + (g)     * AT_PITCH + nt * 8 + 2 * q4) = lo;
            *(uint2*)(sPw + (g + 8) * AT_PITCH + nt * 8 + 2 * q4) = hi;
        }
        __syncwarp();

        // ctx += P @ V : A = P (k = kv), B = V^T (n = hd, k = kv)
#pragma unroll
        for (int kc = 0; kc < 8; kc++) {
            uint32_t a0 = sPw[(g)     * AT_PITCH + kc * 8 + q4];
            uint32_t a1 = sPw[(g + 8) * AT_PITCH + kc * 8 + q4];
            uint32_t a2 = sPw[(g)     * AT_PITCH + kc * 8 + q4 + 4];
            uint32_t a3 = sPw[(g + 8) * AT_PITCH + kc * 8 + q4 + 4];
#pragma unroll
            for (int nt = 0; nt < 8; nt++) {
                uint32_t b0 = sV[(kc * 8 + q4)     * AT_PITCH + nt * 8 + g];
                uint32_t b1 = sV[(kc * 8 + q4 + 4) * AT_PITCH + nt * 8 + g];
                mma_tf32(ctx[nt][0], ctx[nt][1], ctx[nt][2], ctx[nt][3],
                         a0, a1, a2, a3, b0, b1);
            }
        }
        __syncthreads();   // all warps done with sK/sV before next stage
    }

    // epilogue: normalize + store
    float inv0 = 1.0f / l0, inv1 = 1.0f / l1;
    int row0 = qt * 64 + rowW + g;
#pragma unroll
    for (int nt = 0; nt < 8; nt++) {
        int col = nt * 8 + 2 * q4;
        float2 lo = make_float2(ctx[nt][0] * inv0, ctx[nt][1] * inv0);
        float2 hi = make_float2(ctx[nt][2] * inv1, ctx[nt][3] * inv1);
        *(float2*)(Og + headBase + (size_t)row0 * ND + col) = lo;
        *(float2*)(Og + headBase + (size_t)(row0 + 8) * ND + col) = hi;
    }
}

// ---------------------------------------------------------------------------
// Launch:  inputs (metadata order): x, W_q, W_k, W_v, W_o, b_o ; out fp32
// ---------------------------------------------------------------------------
extern "C" void kernel_launch(void* const* d_in, const int* in_sizes, int n_in,
                              void* d_out, int out_size)
{
    const float* x  = (const float*)d_in[0];
    const float* Wq = (const float*)d_in[1];
    const float* Wk = (const float*)d_in[2];
    const float* Wv = (const float*)d_in[3];
    const float* Wo = (const float*)d_in[4];
    const float* bo = (const float*)d_in[5];
    float* out = (float*)d_out;

    float *Qp, *Kp, *Vp, *Cp;
    cudaGetSymbolAddress((void**)&Qp, g_Q);
    cudaGetSymbolAddress((void**)&Kp, g_K);
    cudaGetSymbolAddress((void**)&Vp, g_V);
    cudaGetSymbolAddress((void**)&Cp, g_C);

    cudaFuncSetAttribute(attn_mma,
                         cudaFuncAttributeMaxDynamicSharedMemorySize, AT_SMEM);
    cudaFuncSetAttribute(gemm_mma<false>,
                         cudaFuncAttributeMaxDynamicSharedMemorySize, GEMM_SMEM);
    cudaFuncSetAttribute(gemm_mma<true>,
                         cudaFuncAttributeMaxDynamicSharedMemorySize, GEMM_SMEM);

    dim3 gGemm(ND / 128, MTOT / 128);

    gemm_mma<false><<<gGemm, 256, GEMM_SMEM>>>(x, Wq, nullptr, Qp, ND);
    gemm_mma<false><<<gGemm, 256, GEMM_SMEM>>>(x, Wk, nullptr, Kp, ND);
    gemm_mma<false><<<gGemm, 256, GEMM_SMEM>>>(x, Wv, nullptr, Vp, ND);

    dim3 gAttn(NS / 64, NH, NB);
    attn_mma<<<gAttn, 128, AT_SMEM>>>(Qp, Kp, Vp, Cp);

    gemm_mma<true><<<gGemm, 256, GEMM_SMEM>>>(Cp, Wo, bo, out, ND);
}

// round 9
// speedup vs baseline: 3.0883x; 1.0633x over previous
#include <cuda_runtime.h>
#include <math.h>
#include <cstdint>

// Problem dims (fixed by reference)
#define NB 4
#define NS 2048
#define ND 1024
#define NH 16
#define NHD 64
#define MTOT (NB * NS)   // 8192 rows for the projection GEMMs

// ---------------------------------------------------------------------------
// Scratch (device-global: no cudaMalloc allowed anywhere)
// ---------------------------------------------------------------------------
__device__ float g_Q[NB * NS * ND];
__device__ float g_K[NB * NS * ND];
__device__ float g_V[NB * NS * ND];
__device__ float g_C[NB * NS * ND];
__device__ float g_X[MTOT * ND];     // tf32-rounded x
__device__ float g_Wq[ND * ND];      // tf32-rounded weights
__device__ float g_Wk[ND * ND];
__device__ float g_Wv[ND * ND];
__device__ float g_Wo[ND * ND];

// ---------------------------------------------------------------------------
// Shared helpers
// ---------------------------------------------------------------------------
__device__ __forceinline__ void mma_tf32(
    float& d0, float& d1, float& d2, float& d3,
    uint32_t a0, uint32_t a1, uint32_t a2, uint32_t a3,
    uint32_t b0, uint32_t b1)
{
    asm volatile(
        "mma.sync.aligned.m16n8k8.row.col.f32.tf32.tf32.f32 "
        "{%0,%1,%2,%3}, {%4,%5,%6,%7}, {%8,%9}, {%0,%1,%2,%3};"
        : "+f"(d0), "+f"(d1), "+f"(d2), "+f"(d3)
        : "r"(a0), "r"(a1), "r"(a2), "r"(a3), "r"(b0), "r"(b1));
}

__device__ __forceinline__ uint32_t f2tf32(float x) {
    uint32_t r;
    asm("cvt.rna.tf32.f32 %0, %1;" : "=r"(r) : "f"(x));
    return r;
}

__device__ __forceinline__ uint32_t smem_u32(const void* p) {
    uint32_t a;
    asm("{ .reg .u64 t; cvta.to.shared.u64 t, %1; cvt.u32.u64 %0, t; }"
        : "=r"(a) : "l"(p));
    return a;
}

__device__ __forceinline__ void cp16(uint32_t dst, const void* src) {
    asm volatile("cp.async.cg.shared.global [%0], [%1], 16;"
                 :: "r"(dst), "l"(src));
}
#define CP_COMMIT() asm volatile("cp.async.commit_group;" ::: "memory")
#define CP_WAIT2()  asm volatile("cp.async.wait_group 2;" ::: "memory")

// ---------------------------------------------------------------------------
// Pre-pass: tf32-round a buffer (n multiple of 4)
// ---------------------------------------------------------------------------
__global__ void cvt_tf32(const float* __restrict__ s, float* __restrict__ d, int n)
{
    int i = (blockIdx.x * blockDim.x + threadIdx.x) * 4;
    if (i < n) {
        float4 v = *(const float4*)(s + i);
        uint4 t;
        t.x = f2tf32(v.x); t.y = f2tf32(v.y);
        t.z = f2tf32(v.z); t.w = f2tf32(v.w);
        *(uint4*)(d + i) = t;
    }
}

// ---------------------------------------------------------------------------
// cp.async 3-stage tf32 GEMM (NT): C[m,n] = sum_k A[m,k]*W[n,k] (+bias)
// A, W MUST be pre-tf32-rounded. CTA tile 128x128, BK=32, 256 thr = 8 warps
// (2m x 4n), warp tile 64x32. Row-major smem, pitch 36 words (36 mod 32 = 4
// -> all fragment gathers conflict-free: bank = 4g + q4, bijective).
// ---------------------------------------------------------------------------
#define GP 36                              // pitch (words) for 32-col tile
#define STG_WORDS (2 * 128 * GP)           // A + B per stage = 9216 words
#define GEMM_SMEM (3 * STG_WORDS * 4)      // 110,592 B

__device__ __forceinline__ void gemm_stage(
    uint32_t sbase, const float* __restrict__ A, const float* __restrict__ W,
    int K, int rowBase, int colBase, int k0, int tid)
{
#pragma unroll
    for (int v = 0; v < 4; v++) {
        int f  = tid + v * 256;            // 16B-chunk idx 0..1023
        int r  = f >> 3;                   // row 0..127
        int c4 = (f & 7) << 2;             // col 0,4,..,28
        cp16(sbase + (uint32_t)(r * GP + c4) * 4,
             A + (size_t)(rowBase + r) * K + k0 + c4);
        cp16(sbase + (uint32_t)(128 * GP + r * GP + c4) * 4,
             W + (size_t)(colBase + r) * K + k0 + c4);
    }
}

template <bool BIAS, bool CVTOUT>
__global__ __launch_bounds__(256, 2) void gemm_cp(
    const float* __restrict__ A, const float* __restrict__ W,
    const float* __restrict__ bias, float* __restrict__ C, int K)
{
    extern __shared__ uint32_t smu[];
    const uint32_t sb = smem_u32(smu);

    const int tid  = threadIdx.x;
    const int wid  = tid >> 5;
    const int lane = tid & 31;
    const int g    = lane >> 2;
    const int q4   = lane & 3;
    const int wm   = wid >> 2;             // 0..1
    const int wn   = wid & 3;              // 0..3
    const int rowBase = blockIdx.y * 128;
    const int colBase = blockIdx.x * 128;

    float acc[4][4][4];
#pragma unroll
    for (int i = 0; i < 4; i++)
#pragma unroll
        for (int j = 0; j < 4; j++)
#pragma unroll
            for (int e = 0; e < 4; e++) acc[i][j][e] = 0.0f;

    const int NCH = K / 32;                // 32

    // prologue: stages 0..2 in flight
#pragma unroll
    for (int s = 0; s < 3; s++) {
        gemm_stage(sb + (uint32_t)(s * STG_WORDS) * 4, A, W, K,
                   rowBase, colBase, s * 32, tid);
        CP_COMMIT();
    }

    for (int c = 0; c < NCH; c++) {
        CP_WAIT2();
        __syncthreads();

        const uint32_t* stA = smu + (c % 3) * STG_WORDS;
        const uint32_t* stB = stA + 128 * GP;

#pragma unroll
        for (int kc = 0; kc < 4; kc++) {
            const int kb = kc * 8;
            uint32_t af[4][4], bf[4][2];
#pragma unroll
            for (int mtl = 0; mtl < 4; mtl++) {
                int r0 = wm * 64 + mtl * 16 + g;
                af[mtl][0] = stA[r0 * GP + kb + q4];
                af[mtl][1] = stA[(r0 + 8) * GP + kb + q4];
                af[mtl][2] = stA[r0 * GP + kb + q4 + 4];
                af[mtl][3] = stA[(r0 + 8) * GP + kb + q4 + 4];
            }
#pragma unroll
            for (int ntl = 0; ntl < 4; ntl++) {
                int rb = wn * 32 + ntl * 8 + g;
                bf[ntl][0] = stB[rb * GP + kb + q4];
                bf[ntl][1] = stB[rb * GP + kb + q4 + 4];
            }
#pragma unroll
            for (int mtl = 0; mtl < 4; mtl++)
#pragma unroll
                for (int ntl = 0; ntl < 4; ntl++)
                    mma_tf32(acc[mtl][ntl][0], acc[mtl][ntl][1],
                             acc[mtl][ntl][2], acc[mtl][ntl][3],
                             af[mtl][0], af[mtl][1], af[mtl][2], af[mtl][3],
                             bf[ntl][0], bf[ntl][1]);
        }

        __syncthreads();   // all warps done with stage c%3 before refilling it
        if (c + 3 < NCH)
            gemm_stage(sb + (uint32_t)(((c + 3) % 3) * STG_WORDS) * 4, A, W, K,
                       rowBase, colBase, (c + 3) * 32, tid);
        CP_COMMIT();       // empty group when nothing issued: keeps counts aligned
    }

    // epilogue (validated mapping): row = lane/4 (+8), col = 2*(lane%4) (+1)
    const int rql = lane >> 2;
    const int cql = (lane & 3) * 2;
#pragma unroll
    for (int mtl = 0; mtl < 4; mtl++) {
        int m0 = rowBase + wm * 64 + mtl * 16 + rql;
#pragma unroll
        for (int ntl = 0; ntl < 4; ntl++) {
            int n0 = colBase + wn * 32 + ntl * 8 + cql;
            float b0 = 0.f, b1 = 0.f;
            if (BIAS) { b0 = bias[n0]; b1 = bias[n0 + 1]; }
            float v0 = acc[mtl][ntl][0] + b0, v1 = acc[mtl][ntl][1] + b1;
            float v2 = acc[mtl][ntl][2] + b0, v3 = acc[mtl][ntl][3] + b1;
            if (CVTOUT) {
                v0 = __uint_as_float(f2tf32(v0));
                v1 = __uint_as_float(f2tf32(v1));
                v2 = __uint_as_float(f2tf32(v2));
                v3 = __uint_as_float(f2tf32(v3));
            }
            *(float2*)(C + (size_t)m0 * ND + n0) = make_float2(v0, v1);
            *(float2*)(C + (size_t)(m0 + 8) * ND + n0) = make_float2(v2, v3);
        }
    }
}

// ---------------------------------------------------------------------------
// Tensor-core flash attention (tf32 mma.sync, fp32 softmax, causal).
// Unchanged from R6 (validated) except epilogue writes tf32-rounded ctx so
// the final GEMM can consume it without an in-kernel cvt.
// ---------------------------------------------------------------------------
#define AT_PITCH 68
#define AT_SMEM (4 * 64 * AT_PITCH * 4)   // 69,632 B

__global__ __launch_bounds__(128) void attn_mma(
    const float* __restrict__ Qg, const float* __restrict__ Kg,
    const float* __restrict__ Vg, float* __restrict__ Og)
{
    extern __shared__ uint32_t su[];
    uint32_t* sQ = su;
    uint32_t* sK = sQ + 64 * AT_PITCH;
    uint32_t* sV = sK + 64 * AT_PITCH;
    uint32_t* sP = sV + 64 * AT_PITCH;

    const int qt = blockIdx.x;
    const int h  = blockIdx.y;
    const int b  = blockIdx.z;
    const int tid  = threadIdx.x;
    const int wid  = tid >> 5;
    const int lane = tid & 31;
    const int g    = lane >> 2;
    const int q4   = lane & 3;
    const size_t headBase = ((size_t)b * NS) * ND + (size_t)h * NHD;

    // Load Q tile (64 x 64) -> tf32 smem
#pragma unroll
    for (int v = 0; v < 8; v++) {
        int f = tid + v * 128;
        int r = f >> 4;
        int c = (f & 15) << 2;
        float4 q = *(const float4*)(Qg + headBase + (size_t)(qt * 64 + r) * ND + c);
        uint4 t;
        t.x = f2tf32(q.x); t.y = f2tf32(q.y); t.z = f2tf32(q.z); t.w = f2tf32(q.w);
        *(uint4*)(sQ + r * AT_PITCH + c) = t;
    }

    float m0 = -1e30f, m1 = -1e30f, l0 = 0.0f, l1 = 0.0f;
    float ctx[8][4];
#pragma unroll
    for (int nt = 0; nt < 8; nt++)
#pragma unroll
        for (int e = 0; e < 4; e++) ctx[nt][e] = 0.0f;

    const int rowW = wid * 16;
    uint32_t* sPw = sP + wid * 16 * AT_PITCH;

    for (int jt = 0; jt <= qt; jt++) {
#pragma unroll
        for (int v = 0; v < 8; v++) {
            int f = tid + v * 128;
            int r = f >> 4;
            int c = (f & 15) << 2;
            size_t off = headBase + (size_t)(jt * 64 + r) * ND + c;
            float4 kk = *(const float4*)(Kg + off);
            float4 vv = *(const float4*)(Vg + off);
            uint4 tk, tv;
            tk.x = f2tf32(kk.x); tk.y = f2tf32(kk.y); tk.z = f2tf32(kk.z); tk.w = f2tf32(kk.w);
            tv.x = f2tf32(vv.x); tv.y = f2tf32(vv.y); tv.z = f2tf32(vv.z); tv.w = f2tf32(vv.w);
            *(uint4*)(sK + r * AT_PITCH + c) = tk;
            *(uint4*)(sV + r * AT_PITCH + c) = tv;
        }
        __syncthreads();

        float s[8][4];
#pragma unroll
        for (int nt = 0; nt < 8; nt++)
#pragma unroll
            for (int e = 0; e < 4; e++) s[nt][e] = 0.0f;

#pragma unroll
        for (int kc = 0; kc < 8; kc++) {
            uint32_t a0 = sQ[(rowW + g)     * AT_PITCH + kc * 8 + q4];
            uint32_t a1 = sQ[(rowW + g + 8) * AT_PITCH + kc * 8 + q4];
            uint32_t a2 = sQ[(rowW + g)     * AT_PITCH + kc * 8 + q4 + 4];
            uint32_t a3 = sQ[(rowW + g + 8) * AT_PITCH + kc * 8 + q4 + 4];
#pragma unroll
            for (int nt = 0; nt < 8; nt++) {
                uint32_t b0 = sK[(nt * 8 + g) * AT_PITCH + kc * 8 + q4];
                uint32_t b1 = sK[(nt * 8 + g) * AT_PITCH + kc * 8 + q4 + 4];
                mma_tf32(s[nt][0], s[nt][1], s[nt][2], s[nt][3],
                         a0, a1, a2, a3, b0, b1);
            }
        }

#pragma unroll
        for (int nt = 0; nt < 8; nt++)
#pragma unroll
            for (int e = 0; e < 4; e++) s[nt][e] *= 0.125f;

        if (jt == qt) {
            int r0 = rowW + g, r1 = r0 + 8;
#pragma unroll
            for (int nt = 0; nt < 8; nt++) {
                int c0 = nt * 8 + 2 * q4;
                if (c0     > r0) s[nt][0] = -1e30f;
                if (c0 + 1 > r0) s[nt][1] = -1e30f;
                if (c0     > r1) s[nt][2] = -1e30f;
                if (c0 + 1 > r1) s[nt][3] = -1e30f;
            }
        }

        float mx0 = -1e30f, mx1 = -1e30f;
#pragma unroll
        for (int nt = 0; nt < 8; nt++) {
            mx0 = fmaxf(mx0, fmaxf(s[nt][0], s[nt][1]));
            mx1 = fmaxf(mx1, fmaxf(s[nt][2], s[nt][3]));
        }
        mx0 = fmaxf(mx0, __shfl_xor_sync(0xffffffffu, mx0, 1));
        mx0 = fmaxf(mx0, __shfl_xor_sync(0xffffffffu, mx0, 2));
        mx1 = fmaxf(mx1, __shfl_xor_sync(0xffffffffu, mx1, 1));
        mx1 = fmaxf(mx1, __shfl_xor_sync(0xffffffffu, mx1, 2));

        float mn0 = fmaxf(m0, mx0), mn1 = fmaxf(m1, mx1);
        float cor0 = __expf(m0 - mn0), cor1 = __expf(m1 - mn1);
        l0 *= cor0; l1 *= cor1;
#pragma unroll
        for (int nt = 0; nt < 8; nt++) {
            ctx[nt][0] *= cor0; ctx[nt][1] *= cor0;
            ctx[nt][2] *= cor1; ctx[nt][3] *= cor1;
        }
        float sum0 = 0.0f, sum1 = 0.0f;
#pragma unroll
        for (int nt = 0; nt < 8; nt++) {
            float p0 = __expf(s[nt][0] - mn0);
            float p1 = __expf(s[nt][1] - mn0);
            float p2 = __expf(s[nt][2] - mn1);
            float p3 = __expf(s[nt][3] - mn1);
            s[nt][0] = p0; s[nt][1] = p1; s[nt][2] = p2; s[nt][3] = p3;
            sum0 += p0 + p1; sum1 += p2 + p3;
        }
        sum0 += __shfl_xor_sync(0xffffffffu, sum0, 1);
        sum0 += __shfl_xor_sync(0xffffffffu, sum0, 2);
        sum1 += __shfl_xor_sync(0xffffffffu, sum1, 1);
        sum1 += __shfl_xor_sync(0xffffffffu, sum1, 2);
        l0 += sum0; l1 += sum1;
        m0 = mn0; m1 = mn1;

#pragma unroll
        for (int nt = 0; nt < 8; nt++) {
            uint2 lo = make_uint2(f2tf32(s[nt][0]), f2tf32(s[nt][1]));
            uint2 hi = make_uint2(f2tf32(s[nt][2]), f2tf32(s[nt][3]));
            *(uint2*)(sPw + (g)     * AT_PITCH + nt * 8 + 2 * q4) = lo;
            *(uint2*)(sPw + (g + 8) * AT_PITCH + nt * 8 + 2 * q4) = hi;
        }
        __syncwarp();

#pragma unroll
        for (int kc = 0; kc < 8; kc++) {
            uint32_t a0 = sPw[(g)     * AT_PITCH + kc * 8 + q4];
            uint32_t a1 = sPw[(g + 8) * AT_PITCH + kc * 8 + q4];
            uint32_t a2 = sPw[(g)     * AT_PITCH + kc * 8 + q4 + 4];
            uint32_t a3 = sPw[(g + 8) * AT_PITCH + kc * 8 + q4 + 4];
#pragma unroll
            for (int nt = 0; nt < 8; nt++) {
                uint32_t b0 = sV[(kc * 8 + q4)     * AT_PITCH + nt * 8 + g];
                uint32_t b1 = sV[(kc * 8 + q4 + 4) * AT_PITCH + nt * 8 + g];
                mma_tf32(ctx[nt][0], ctx[nt][1], ctx[nt][2], ctx[nt][3],
                         a0, a1, a2, a3, b0, b1);
            }
        }
        __syncthreads();
    }

    // epilogue: normalize + tf32-round (feeds the final cp.async GEMM)
    float inv0 = 1.0f / l0, inv1 = 1.0f / l1;
    int row0 = qt * 64 + rowW + g;
#pragma unroll
    for (int nt = 0; nt < 8; nt++) {
        int col = nt * 8 + 2 * q4;
        float2 lo = make_float2(__uint_as_float(f2tf32(ctx[nt][0] * inv0)),
                                __uint_as_float(f2tf32(ctx[nt][1] * inv0)));
        float2 hi = make_float2(__uint_as_float(f2tf32(ctx[nt][2] * inv1)),
                                __uint_as_float(f2tf32(ctx[nt][3] * inv1)));
        *(float2*)(Og + headBase + (size_t)row0 * ND + col) = lo;
        *(float2*)(Og + headBase + (size_t)(row0 + 8) * ND + col) = hi;
    }
}

// ---------------------------------------------------------------------------
// Launch:  inputs (metadata order): x, W_q, W_k, W_v, W_o, b_o ; out fp32
// ---------------------------------------------------------------------------
extern "C" void kernel_launch(void* const* d_in, const int* in_sizes, int n_in,
                              void* d_out, int out_size)
{
    const float* x  = (const float*)d_in[0];
    const float* Wq = (const float*)d_in[1];
    const float* Wk = (const float*)d_in[2];
    const float* Wv = (const float*)d_in[3];
    const float* Wo = (const float*)d_in[4];
    const float* bo = (const float*)d_in[5];
    float* out = (float*)d_out;

    float *Qp, *Kp, *Vp, *Cp, *Xp, *Wqp, *Wkp, *Wvp, *Wop;
    cudaGetSymbolAddress((void**)&Qp,  g_Q);
    cudaGetSymbolAddress((void**)&Kp,  g_K);
    cudaGetSymbolAddress((void**)&Vp,  g_V);
    cudaGetSymbolAddress((void**)&Cp,  g_C);
    cudaGetSymbolAddress((void**)&Xp,  g_X);
    cudaGetSymbolAddress((void**)&Wqp, g_Wq);
    cudaGetSymbolAddress((void**)&Wkp, g_Wk);
    cudaGetSymbolAddress((void**)&Wvp, g_Wv);
    cudaGetSymbolAddress((void**)&Wop, g_Wo);

    cudaFuncSetAttribute(attn_mma,
                         cudaFuncAttributeMaxDynamicSharedMemorySize, AT_SMEM);
    cudaFuncSetAttribute(gemm_cp<false, true>,
                         cudaFuncAttributeMaxDynamicSharedMemorySize, GEMM_SMEM);
    cudaFuncSetAttribute(gemm_cp<true, false>,
                         cudaFuncAttributeMaxDynamicSharedMemorySize, GEMM_SMEM);

    // pre-pass: tf32-round inputs once
    const int nx = MTOT * ND;   // 8,388,608
    const int nw = ND * ND;     // 1,048,576
    cvt_tf32<<<nx / 4 / 256, 256>>>(x,  Xp,  nx);
    cvt_tf32<<<nw / 4 / 256, 256>>>(Wq, Wqp, nw);
    cvt_tf32<<<nw / 4 / 256, 256>>>(Wk, Wkp, nw);
    cvt_tf32<<<nw / 4 / 256, 256>>>(Wv, Wvp, nw);
    cvt_tf32<<<nw / 4 / 256, 256>>>(Wo, Wop, nw);

    dim3 gGemm(ND / 128, MTOT / 128);

    gemm_cp<false, true><<<gGemm, 256, GEMM_SMEM>>>(Xp, Wqp, nullptr, Qp, ND);
    gemm_cp<false, true><<<gGemm, 256, GEMM_SMEM>>>(Xp, Wkp, nullptr, Kp, ND);
    gemm_cp<false, true><<<gGemm, 256, GEMM_SMEM>>>(Xp, Wvp, nullptr, Vp, ND);

    dim3 gAttn(NS / 64, NH, NB);
    attn_mma<<<gAttn, 128, AT_SMEM>>>(Qp, Kp, Vp, Cp);

    gemm_cp<true, false><<<gGemm, 256, GEMM_SMEM>>>(Cp, Wop, bo, out, ND);
}